// round 2
// baseline (speedup 1.0000x reference)
#include <cuda_runtime.h>

// Problem constants
#define NB 2
#define NT 2048
#define NC 1024
#define NH 16
#define ND 64
#define NP 16
#define NS 2064      // NP + NT
#define NROWS 4096   // NB * NT

// Scratch (allocation-free: __device__ globals)
__device__ float g_q[NB*NH*NT*ND];      // [b,h,t,d], pre-scaled by 1/8
__device__ float g_k[NB*NH*NS*ND];      // [b,h,s,d]  (s = prefix ++ t)
__device__ float g_v[NB*NH*NS*ND];
__device__ float g_att[(size_t)NROWS*NC]; // [b,t, h*64+d]

// ---------------------------------------------------------------------------
// Prefix broadcast: prefix_k/v [1,16,16,64] -> g_k/g_v[:, :, 0:16, :] for both b
// ---------------------------------------------------------------------------
__global__ void prefix_fill_kernel(const float* __restrict__ pk,
                                   const float* __restrict__ pv) {
    int idx = blockIdx.x * blockDim.x + threadIdx.x;
    if (idx >= NH*NP*ND) return;
    int d = idx & (ND-1);
    int p = (idx >> 6) & (NP-1);
    int h = idx >> 10;
    float kval = pk[idx];
    float vval = pv[idx];
#pragma unroll
    for (int b = 0; b < NB; b++) {
        int o = ((b*NH + h)*NS + p)*ND + d;
        g_k[o] = kval;
        g_v[o] = vval;
    }
}

// ---------------------------------------------------------------------------
// SGEMM 128x128x8, 256 threads, 8x8 per thread, fp32.
// MODE 0: A = x [4096,1024], W = W_qkv [1024,3072]; epilogue adds bias and
//         scatters q (scaled by 0.125) / k / v into [B,H,(P+)T,D] buffers.
// MODE 1: A = g_att [4096,1024], W = W_out [1024,1024]; epilogue adds bias,
//         writes d_out.
// ---------------------------------------------------------------------------
template<int MODE>
__global__ __launch_bounds__(256) void gemm_kernel(const float* __restrict__ A,
                                                   const float* __restrict__ W,
                                                   const float* __restrict__ bias,
                                                   float* __restrict__ out) {
    const int LDW = (MODE == 0) ? 3*NC : NC;
    __shared__ float As[8][128];
    __shared__ float Bs[8][128];
    const float* Ap = (MODE == 0) ? A : g_att;
    const int r0 = blockIdx.y * 128;
    const int c0 = blockIdx.x * 128;
    const int tid = threadIdx.x;
    const int ty = tid >> 4, tx = tid & 15;
    const int arow = tid >> 1, acol = (tid & 1) * 4;
    const int brow = tid >> 5, bcol = (tid & 31) * 4;
    const float* Aload = Ap + (size_t)(r0 + arow) * NC + acol;
    const float* Wload = W + (size_t)brow * LDW + c0 + bcol;

    float acc[8][8];
#pragma unroll
    for (int i = 0; i < 8; i++)
#pragma unroll
        for (int j = 0; j < 8; j++) acc[i][j] = 0.f;

    float4 av = *(const float4*)Aload;
    float4 bv = *(const float4*)Wload;
    for (int k0 = 0; k0 < NC; k0 += 8) {
        As[acol+0][arow] = av.x;
        As[acol+1][arow] = av.y;
        As[acol+2][arow] = av.z;
        As[acol+3][arow] = av.w;
        *(float4*)&Bs[brow][bcol] = bv;
        __syncthreads();
        if (k0 + 8 < NC) {
            av = *(const float4*)(Aload + k0 + 8);
            bv = *(const float4*)(Wload + (size_t)(k0 + 8) * LDW);
        }
#pragma unroll
        for (int k = 0; k < 8; k++) {
            float a[8], b[8];
            *(float4*)(a)     = *(const float4*)&As[k][ty*8];
            *(float4*)(a + 4) = *(const float4*)&As[k][ty*8 + 4];
            *(float4*)(b)     = *(const float4*)&Bs[k][tx*8];
            *(float4*)(b + 4) = *(const float4*)&Bs[k][tx*8 + 4];
#pragma unroll
            for (int i = 0; i < 8; i++)
#pragma unroll
                for (int j = 0; j < 8; j++)
                    acc[i][j] = fmaf(a[i], b[j], acc[i][j]);
        }
        __syncthreads();
    }

    const int cbase = c0 + tx * 8;
    float bb[8];
#pragma unroll
    for (int j = 0; j < 8; j++) bb[j] = bias[cbase + j];

    if (MODE == 1) {
#pragma unroll
        for (int i = 0; i < 8; i++) {
            int r = r0 + ty*8 + i;
            float v[8];
#pragma unroll
            for (int j = 0; j < 8; j++) v[j] = acc[i][j] + bb[j];
            *(float4*)&out[(size_t)r*NC + cbase]     = *(float4*)(v);
            *(float4*)&out[(size_t)r*NC + cbase + 4] = *(float4*)(v + 4);
        }
    } else {
        // each thread's 8 columns lie inside one (which, head) 64-col block
        const int which = cbase >> 10;       // 0=q, 1=k, 2=v
        const int h  = (cbase >> 6) & (NH-1);
        const int dl = cbase & (ND-1);
#pragma unroll
        for (int i = 0; i < 8; i++) {
            int r = r0 + ty*8 + i;
            int b = r >> 11;
            int t = r & (NT-1);
            float v[8];
#pragma unroll
            for (int j = 0; j < 8; j++) v[j] = acc[i][j] + bb[j];
            if (which == 0) {
#pragma unroll
                for (int j = 0; j < 8; j++) v[j] *= 0.125f;   // 1/sqrt(64)
                size_t o = ((size_t)(b*NH + h)*NT + t)*ND + dl;
                *(float4*)&g_q[o]     = *(float4*)(v);
                *(float4*)&g_q[o + 4] = *(float4*)(v + 4);
            } else {
                size_t o = ((size_t)(b*NH + h)*NS + NP + t)*ND + dl;
                float* dst = (which == 1) ? g_k : g_v;
                *(float4*)&dst[o]     = *(float4*)(v);
                *(float4*)&dst[o + 4] = *(float4*)(v + 4);
            }
        }
    }
}

// ---------------------------------------------------------------------------
// Flash attention, fp32, full (non-causal) softmax over S=2064 keys.
// Block = one (b,h) x 64-query tile. 256 threads, 4x4 register tiles.
// smem: Qs[64][65], Ks[64][65] (reused as P[64][64]), Vs[64][64] = 49664 B.
// ---------------------------------------------------------------------------
#define ATTN_SMEM ((64*65 + 64*65 + 64*64) * 4)

__global__ __launch_bounds__(256) void attn_kernel() {
    extern __shared__ float sm[];
    float* Qs = sm;               // stride 65
    float* Ks = sm + 64*65;       // stride 65 for K; reused stride 64 for P
    float* Vs = sm + 2*64*65;     // stride 64

    const int bh = blockIdx.y;
    const int q0 = blockIdx.x * 64;
    const int b = bh >> 4, h = bh & (NH-1);
    const float* Qp = g_q + ((size_t)bh * NT + q0) * ND;
    const float* Kp = g_k + (size_t)bh * NS * ND;
    const float* Vp = g_v + (size_t)bh * NS * ND;
    const int tid = threadIdx.x;
    const int ty = tid >> 4, tx = tid & 15;

    // load Q tile [64 x 64] (q already scaled by 1/8)
#pragma unroll
    for (int it = 0; it < 4; it++) {
        int i = tid + it * 256;
        int m = i >> 4, d4 = (i & 15) * 4;
        float4 qv = *(const float4*)(Qp + m*ND + d4);
        Qs[m*65 + d4 + 0] = qv.x;
        Qs[m*65 + d4 + 1] = qv.y;
        Qs[m*65 + d4 + 2] = qv.z;
        Qs[m*65 + d4 + 3] = qv.w;
    }

    float mreg[4], lreg[4], o[4][4];
#pragma unroll
    for (int i = 0; i < 4; i++) {
        mreg[i] = -1e30f; lreg[i] = 0.f;
#pragma unroll
        for (int c = 0; c < 4; c++) o[i][c] = 0.f;
    }

    for (int s0 = 0; s0 < NS; s0 += 64) {
        // load K,V tiles (zero-fill past S)
#pragma unroll
        for (int it = 0; it < 4; it++) {
            int i = tid + it * 256;
            int n = i >> 4, d4 = (i & 15) * 4;
            float4 kv, vv;
            if (s0 + n < NS) {
                kv = *(const float4*)(Kp + (size_t)(s0 + n)*ND + d4);
                vv = *(const float4*)(Vp + (size_t)(s0 + n)*ND + d4);
            } else {
                kv = make_float4(0.f,0.f,0.f,0.f);
                vv = make_float4(0.f,0.f,0.f,0.f);
            }
            Ks[n*65 + d4 + 0] = kv.x;
            Ks[n*65 + d4 + 1] = kv.y;
            Ks[n*65 + d4 + 2] = kv.z;
            Ks[n*65 + d4 + 3] = kv.w;
            *(float4*)&Vs[n*64 + d4] = vv;
        }
        __syncthreads();

        // S = Q K^T  (64x64 tile; thread owns rows ty*4.., cols tx*4..)
        float sacc[4][4];
#pragma unroll
        for (int i = 0; i < 4; i++)
#pragma unroll
            for (int j = 0; j < 4; j++) sacc[i][j] = 0.f;
#pragma unroll 8
        for (int d = 0; d < 64; d++) {
            float qa[4], kb[4];
#pragma unroll
            for (int i = 0; i < 4; i++) qa[i] = Qs[(ty*4+i)*65 + d];
#pragma unroll
            for (int j = 0; j < 4; j++) kb[j] = Ks[(tx*4+j)*65 + d];
#pragma unroll
            for (int i = 0; i < 4; i++)
#pragma unroll
                for (int j = 0; j < 4; j++)
                    sacc[i][j] = fmaf(qa[i], kb[j], sacc[i][j]);
        }
        if (s0 + 64 > NS) {
#pragma unroll
            for (int j = 0; j < 4; j++)
                if (s0 + tx*4 + j >= NS) {
#pragma unroll
                    for (int i = 0; i < 4; i++) sacc[i][j] = -1e30f;
                }
        }
        __syncthreads();   // all Ks reads done before P overwrites it

        // online softmax (row stats replicated across the 16 tx lanes)
        float p[4][4];
#pragma unroll
        for (int i = 0; i < 4; i++) {
            float rmax = fmaxf(fmaxf(sacc[i][0], sacc[i][1]),
                               fmaxf(sacc[i][2], sacc[i][3]));
#pragma unroll
            for (int off = 8; off >= 1; off >>= 1)
                rmax = fmaxf(rmax, __shfl_xor_sync(0xffffffffu, rmax, off, 16));
            float mnew = fmaxf(mreg[i], rmax);
            float alpha = __expf(mreg[i] - mnew);
            float ps = 0.f;
#pragma unroll
            for (int j = 0; j < 4; j++) {
                p[i][j] = __expf(sacc[i][j] - mnew);
                ps += p[i][j];
            }
#pragma unroll
            for (int off = 8; off >= 1; off >>= 1)
                ps += __shfl_xor_sync(0xffffffffu, ps, off, 16);
            lreg[i] = lreg[i]*alpha + ps;
            mreg[i] = mnew;
#pragma unroll
            for (int c = 0; c < 4; c++) o[i][c] *= alpha;
        }
        // stage P into (former) K smem, stride 64 (float4 stores, conflict-free)
#pragma unroll
        for (int i = 0; i < 4; i++)
            *(float4*)&Ks[(ty*4+i)*64 + tx*4] = *(float4*)p[i];
        __syncthreads();

        // O += P @ V
#pragma unroll 8
        for (int j = 0; j < 64; j++) {
            float pv0[4], vb[4];
#pragma unroll
            for (int i = 0; i < 4; i++) pv0[i] = Ks[(ty*4+i)*64 + j];
            *(float4*)vb = *(const float4*)&Vs[j*64 + tx*4];
#pragma unroll
            for (int i = 0; i < 4; i++)
#pragma unroll
                for (int c = 0; c < 4; c++)
                    o[i][c] = fmaf(pv0[i], vb[c], o[i][c]);
        }
        __syncthreads();
    }

    // epilogue: normalize and write [b, t, h*64+d]
#pragma unroll
    for (int i = 0; i < 4; i++) {
        float inv = 1.f / lreg[i];
        int t = q0 + ty*4 + i;
        float v[4];
#pragma unroll
        for (int c = 0; c < 4; c++) v[c] = o[i][c] * inv;
        *(float4*)&g_att[((size_t)(b*NT + t))*NC + h*ND + tx*4] = *(float4*)v;
    }
}

// ---------------------------------------------------------------------------
// Launch: prefix fill -> QKV GEMM+scatter -> flash attention -> out GEMM
// All on the capture stream; graph-capturable (no sync, no alloc).
// ---------------------------------------------------------------------------
extern "C" void kernel_launch(void* const* d_in, const int* in_sizes, int n_in,
                              void* d_out, int out_size) {
    const float* x    = (const float*)d_in[0];
    const float* pk   = (const float*)d_in[1];
    const float* pv   = (const float*)d_in[2];
    const float* Wqkv = (const float*)d_in[3];
    const float* bqkv = (const float*)d_in[4];
    const float* Wout = (const float*)d_in[5];
    const float* bout = (const float*)d_in[6];
    float* out = (float*)d_out;

    cudaFuncSetAttribute(attn_kernel,
                         cudaFuncAttributeMaxDynamicSharedMemorySize, ATTN_SMEM);

    prefix_fill_kernel<<<64, 256>>>(pk, pv);
    gemm_kernel<0><<<dim3(24, 32), 256>>>(x, Wqkv, bqkv, nullptr);
    attn_kernel<<<dim3(32, 32), 256, ATTN_SMEM>>>();
    gemm_kernel<1><<<dim3(8, 32), 256>>>(nullptr, Wout, bout, out);
}

// round 5
// speedup vs baseline: 1.3571x; 1.3571x over previous
#include <cuda_runtime.h>
#include <cuda_bf16.h>
#include <cstdint>

// Problem constants
#define NB 2
#define NT 2048
#define NC 1024
#define NH 16
#define ND 64
#define NP 16
#define NS 2064      // NP + NT
#define NROWS 4096   // NB * NT

// ---------------------------------------------------------------------------
// Scratch (allocation-free: __device__ globals)
// ---------------------------------------------------------------------------
__device__ float g_q[NB*NH*NT*ND];        // [b,h,t,d], pre-scaled by 1/8
__device__ float g_k[NB*NH*NS*ND];        // [b,h,s,d]  (s = prefix ++ t)
__device__ float g_v[NB*NH*NS*ND];
__device__ float g_att[(size_t)NROWS*NC]; // [b,t, h*64+d]
// Pre-transposed + hi/lo-split weights, [N][K] bf16 (K = 1024 for both)
__device__ unsigned short g_wqkv_h[3*NC*NC];
__device__ unsigned short g_wqkv_l[3*NC*NC];
__device__ unsigned short g_wout_h[NC*NC];
__device__ unsigned short g_wout_l[NC*NC];

// ---------------------------------------------------------------------------
// Helpers (family-agnostic: ldmatrix / mma.sync / cp.async only — NO tcgen05)
// ---------------------------------------------------------------------------
__device__ __forceinline__ uint32_t smem_u32(const void* p) {
    uint32_t a;
    asm("{ .reg .u64 t; cvta.to.shared.u64 t, %1; cvt.u32.u64 %0, t; }" : "=r"(a) : "l"(p));
    return a;
}

#define STS128(addr, a, b, c, d) \
    asm volatile("st.shared.v4.b32 [%0], {%1,%2,%3,%4};" :: "r"(addr), "r"(a), "r"(b), "r"(c), "r"(d) : "memory")

#define CP_ASYNC16(dst, src) \
    asm volatile("cp.async.cg.shared.global [%0], [%1], 16;" :: "r"(dst), "l"(src) : "memory")
#define CP_COMMIT() asm volatile("cp.async.commit_group;" ::: "memory")
#define CP_WAIT0()  asm volatile("cp.async.wait_group 0;" ::: "memory")

// SW128 swizzle: bits[6:4] ^= bits[9:7] (16B-chunk xor within 128B rows)
#define SW128(o) ((o) ^ (((o) >> 3) & 0x70))
__device__ __forceinline__ uint32_t swz(uint32_t base, uint32_t off) {
    return base + SW128(off);
}

__device__ __forceinline__ void ldsm_x4(uint32_t& r0, uint32_t& r1, uint32_t& r2, uint32_t& r3,
                                        uint32_t addr) {
    asm volatile("ldmatrix.sync.aligned.m8n8.x4.shared.b16 {%0,%1,%2,%3}, [%4];"
                 : "=r"(r0), "=r"(r1), "=r"(r2), "=r"(r3) : "r"(addr));
}

__device__ __forceinline__ void mma16816(float* d, const uint32_t* a, const uint32_t* b) {
    asm volatile("mma.sync.aligned.m16n8k16.row.col.f32.bf16.bf16.f32 "
                 "{%0,%1,%2,%3}, {%4,%5,%6,%7}, {%8,%9}, {%0,%1,%2,%3};"
                 : "+f"(d[0]), "+f"(d[1]), "+f"(d[2]), "+f"(d[3])
                 : "r"(a[0]), "r"(a[1]), "r"(a[2]), "r"(a[3]), "r"(b[0]), "r"(b[1]));
}

// hi/lo bf16 split of two floats, packed into two u32 (low element in low half)
__device__ __forceinline__ void cvt2(float a, float b, uint32_t& h, uint32_t& l) {
    __nv_bfloat16 ha = __float2bfloat16_rn(a);
    __nv_bfloat16 hb = __float2bfloat16_rn(b);
    __nv_bfloat16 la = __float2bfloat16_rn(a - __bfloat162float(ha));
    __nv_bfloat16 lb = __float2bfloat16_rn(b - __bfloat162float(hb));
    h = ((uint32_t)__bfloat16_as_ushort(hb) << 16) | (uint32_t)__bfloat16_as_ushort(ha);
    l = ((uint32_t)__bfloat16_as_ushort(lb) << 16) | (uint32_t)__bfloat16_as_ushort(la);
}

// ---------------------------------------------------------------------------
// Weight prep: W [K=1024][N] fp32 -> Wt_h/Wt_l [N][1024] bf16 (hi/lo split)
// ---------------------------------------------------------------------------
__global__ void wprep_kernel(const float* __restrict__ W, int N,
                             unsigned short* __restrict__ Wt_h,
                             unsigned short* __restrict__ Wt_l) {
    __shared__ float tile[32][33];
    const int n0 = blockIdx.x * 32, k0 = blockIdx.y * 32;
    const int tx = threadIdx.x, ty = threadIdx.y;  // 32 x 8
#pragma unroll
    for (int i = 0; i < 32; i += 8)
        tile[ty + i][tx] = W[(size_t)(k0 + ty + i) * N + n0 + tx];
    __syncthreads();
#pragma unroll
    for (int i = 0; i < 32; i += 8) {
        float v = tile[tx][ty + i];                 // = W[k0+tx][n0+ty+i]
        __nv_bfloat16 h = __float2bfloat16_rn(v);
        __nv_bfloat16 l = __float2bfloat16_rn(v - __bfloat162float(h));
        size_t o = (size_t)(n0 + ty + i) * NC + k0 + tx;
        Wt_h[o] = __bfloat16_as_ushort(h);
        Wt_l[o] = __bfloat16_as_ushort(l);
    }
}

// ---------------------------------------------------------------------------
// Prefix broadcast
// ---------------------------------------------------------------------------
__global__ void prefix_fill_kernel(const float* __restrict__ pk,
                                   const float* __restrict__ pv) {
    int idx = blockIdx.x * blockDim.x + threadIdx.x;
    if (idx >= NH*NP*ND) return;
    int d = idx & (ND-1);
    int p = (idx >> 6) & (NP-1);
    int h = idx >> 10;
    float kval = pk[idx];
    float vval = pv[idx];
#pragma unroll
    for (int b = 0; b < NB; b++) {
        int o = ((b*NH + h)*NS + p)*ND + d;
        g_k[o] = kval;
        g_v[o] = vval;
    }
}

// ---------------------------------------------------------------------------
// mma.sync GEMM: C[M,N] = A[M,1024] @ Wt^T  with 3-term bf16 split.
// CTA = 128x128 tile, 256 threads = 8 warps (4m x 2n), warp tile 32x64.
// K chunks of 64, double-buffered smem. B via cp.async, A via reg staging.
// smem per buffer: Ah 16K | Al 16K | Bh 16K | Bl 16K  (x2 = 128KB)
// MODE 0: A = x, W = qkv; epilogue scatters q (x0.125) / k / v (+bias).
// MODE 1: A = g_att, W = out; epilogue adds bias, writes d_out.
// ---------------------------------------------------------------------------
#define GEMM_SMEM (2*65536 + 1024)
#define NCH 16

__device__ __forceinline__ void qkv_scatter(int row, int col, float x, float y) {
    const int which = col >> 10;            // 0=q 1=k 2=v
    const int h  = (col >> 6) & (NH - 1);
    const int dl = col & (ND - 1);
    const int b = row >> 11;
    const int t = row & (NT - 1);
    float2 v;
    if (which == 0) {
        v.x = x * 0.125f; v.y = y * 0.125f;
        *(float2*)&g_q[((size_t)(b*NH + h)*NT + t)*ND + dl] = v;
    } else {
        v.x = x; v.y = y;
        float* dst = (which == 1) ? g_k : g_v;
        *(float2*)&dst[((size_t)(b*NH + h)*NS + NP + t)*ND + dl] = v;
    }
}

template<int MODE>
__global__ __launch_bounds__(256) void mma_gemm_kernel(const float* __restrict__ A,
                                                       const float* __restrict__ bias,
                                                       float* __restrict__ out) {
    extern __shared__ char dsm[];
    const uint32_t sb = (smem_u32(dsm) + 1023u) & ~1023u;

    const int tid = threadIdx.x;
    const int lane = tid & 31;
    const int wm = (tid >> 5) & 3;          // warp m index (0..3)
    const int wn = tid >> 7;                // warp n index (0..1)
    const int r0 = blockIdx.y * 128;
    const int c0 = blockIdx.x * 128;

    const float* Ap = (MODE == 0) ? A : g_att;
    const unsigned short* Wh = (MODE == 0) ? g_wqkv_h : g_wout_h;
    const unsigned short* Wl = (MODE == 0) ? g_wqkv_l : g_wout_l;

    // ldmatrix per-lane base offsets (bytes, pre-swizzle)
    const uint32_t a_off = (uint32_t)((32*wm + (lane & 15)) * 128 + (lane >> 4) * 16);
    const uint32_t b_off = (uint32_t)((64*wn + ((lane >> 4) & 1) * 8 + (lane & 7)) * 128
                                      + ((lane >> 3) & 1) * 16);

    // Load/store index mapping (8 elems per thread per iter, 4 iters)
    const int ldrow = tid >> 3;             // 0..31 (+32/iter)
    const int ldc8  = (tid & 7) * 8;        // 0..56

    float acc[2][8][4];
#pragma unroll
    for (int mf = 0; mf < 2; mf++)
#pragma unroll
        for (int ng = 0; ng < 8; ng++)
#pragma unroll
            for (int c = 0; c < 4; c++) acc[mf][ng][c] = 0.f;

    float4 av[4][2];

    // ---- load helpers (inlined via lambdas would hurt; write explicit) ----
    // B async copy for chunk ch into buffer base 'bb'
    auto loadB = [&](int ch, uint32_t bb) {
#pragma unroll
        for (int it = 0; it < 4; ++it) {
            int n  = ldrow + it * 32;
            size_t go = (size_t)(c0 + n) * NC + ch * 64 + ldc8;
            uint32_t off = SW128((uint32_t)(n * 128 + ldc8 * 2));
            CP_ASYNC16(bb + 32768u + off, Wh + go);
            CP_ASYNC16(bb + 49152u + off, Wl + go);
        }
    };
    auto loadA = [&](int ch) {
#pragma unroll
        for (int it = 0; it < 4; ++it) {
            int row = ldrow + it * 32;
            const float* ap = Ap + (size_t)(r0 + row) * NC + ch * 64 + ldc8;
            av[it][0] = *(const float4*)ap;
            av[it][1] = *(const float4*)(ap + 4);
        }
    };
    auto stsA = [&](uint32_t bb) {
#pragma unroll
        for (int it = 0; it < 4; ++it) {
            int row = ldrow + it * 32;
            uint32_t h[4], l[4];
            cvt2(av[it][0].x, av[it][0].y, h[0], l[0]);
            cvt2(av[it][0].z, av[it][0].w, h[1], l[1]);
            cvt2(av[it][1].x, av[it][1].y, h[2], l[2]);
            cvt2(av[it][1].z, av[it][1].w, h[3], l[3]);
            uint32_t off = SW128((uint32_t)(row * 128 + ldc8 * 2));
            STS128(bb + off,          h[0], h[1], h[2], h[3]);
            STS128(bb + 16384u + off, l[0], l[1], l[2], l[3]);
        }
    };

    // ---- prologue: chunk 0 ----
    loadB(0, sb);
    CP_COMMIT();
    loadA(0);
    stsA(sb);
    CP_WAIT0();
    __syncthreads();

    for (int ch = 0; ch < NCH; ++ch) {
        const uint32_t base = sb + (uint32_t)(ch & 1) * 65536u;
        const uint32_t nbase = sb + (uint32_t)((ch & 1) ^ 1) * 65536u;

        if (ch + 1 < NCH) {
            loadB(ch + 1, nbase);
            CP_COMMIT();
            loadA(ch + 1);
        }

        // ---- compute this chunk ----
        const uint32_t bAh = base, bAl = base + 16384u;
        const uint32_t bBh = base + 32768u, bBl = base + 49152u;
#pragma unroll
        for (int kk = 0; kk < 4; ++kk) {
            uint32_t Ah[2][4], Al[2][4];
#pragma unroll
            for (int mf = 0; mf < 2; mf++) {
                uint32_t o = a_off + kk * 32 + mf * 2048;
                ldsm_x4(Ah[mf][0], Ah[mf][1], Ah[mf][2], Ah[mf][3], swz(bAh, o));
                ldsm_x4(Al[mf][0], Al[mf][1], Al[mf][2], Al[mf][3], swz(bAl, o));
            }
#pragma unroll
            for (int g = 0; g < 4; ++g) {
                uint32_t Bh[4], Bl[4];
                uint32_t o = b_off + g * 2048 + kk * 32;
                ldsm_x4(Bh[0], Bh[1], Bh[2], Bh[3], swz(bBh, o));
                ldsm_x4(Bl[0], Bl[1], Bl[2], Bl[3], swz(bBl, o));
                // pass 1: Ah*Bh (4 independent tiles)
#pragma unroll
                for (int mf = 0; mf < 2; mf++) {
                    mma16816(acc[mf][2*g],   Ah[mf], Bh);
                    mma16816(acc[mf][2*g+1], Ah[mf], Bh + 2);
                }
                // pass 2: Al*Bh
#pragma unroll
                for (int mf = 0; mf < 2; mf++) {
                    mma16816(acc[mf][2*g],   Al[mf], Bh);
                    mma16816(acc[mf][2*g+1], Al[mf], Bh + 2);
                }
                // pass 3: Ah*Bl
#pragma unroll
                for (int mf = 0; mf < 2; mf++) {
                    mma16816(acc[mf][2*g],   Ah[mf], Bl);
                    mma16816(acc[mf][2*g+1], Ah[mf], Bl + 2);
                }
            }
        }

        if (ch + 1 < NCH) {
            stsA(nbase);
            CP_WAIT0();
            __syncthreads();
        }
    }

    // ---- epilogue ----
    const int g4 = lane >> 2, t4 = lane & 3;
    const int colb = c0 + 64 * wn;
#pragma unroll
    for (int ng = 0; ng < 8; ++ng) {
        const int col = colb + 8 * ng + 2 * t4;
        const float b0v = bias[col], b1v = bias[col + 1];
#pragma unroll
        for (int mf = 0; mf < 2; mf++) {
            const int row = r0 + 32 * wm + 16 * mf + g4;
            const float* ac = acc[mf][ng];
            if (MODE == 1) {
                float2 v0 = make_float2(ac[0] + b0v, ac[1] + b1v);
                float2 v1 = make_float2(ac[2] + b0v, ac[3] + b1v);
                *(float2*)&out[(size_t)row * NC + col] = v0;
                *(float2*)&out[(size_t)(row + 8) * NC + col] = v1;
            } else {
                qkv_scatter(row,     col, ac[0] + b0v, ac[1] + b1v);
                qkv_scatter(row + 8, col, ac[2] + b0v, ac[3] + b1v);
            }
        }
    }
}

// ---------------------------------------------------------------------------
// Flash attention, fp32 SIMT (unchanged from passing R1 kernel)
// ---------------------------------------------------------------------------
#define ATTN_SMEM ((64*65 + 64*65 + 64*64) * 4)

__global__ __launch_bounds__(256) void attn_kernel() {
    extern __shared__ float sm[];
    float* Qs = sm;               // stride 65
    float* Ks = sm + 64*65;       // stride 65 for K; reused stride 64 for P
    float* Vs = sm + 2*64*65;     // stride 64

    const int bh = blockIdx.y;
    const int q0 = blockIdx.x * 64;
    const int b = bh >> 4, h = bh & (NH-1);
    const float* Qp = g_q + ((size_t)bh * NT + q0) * ND;
    const float* Kp = g_k + (size_t)bh * NS * ND;
    const float* Vp = g_v + (size_t)bh * NS * ND;
    const int tid = threadIdx.x;
    const int ty = tid >> 4, tx = tid & 15;

#pragma unroll
    for (int it = 0; it < 4; it++) {
        int i = tid + it * 256;
        int m = i >> 4, d4 = (i & 15) * 4;
        float4 qv = *(const float4*)(Qp + m*ND + d4);
        Qs[m*65 + d4 + 0] = qv.x;
        Qs[m*65 + d4 + 1] = qv.y;
        Qs[m*65 + d4 + 2] = qv.z;
        Qs[m*65 + d4 + 3] = qv.w;
    }

    float mreg[4], lreg[4], o[4][4];
#pragma unroll
    for (int i = 0; i < 4; i++) {
        mreg[i] = -1e30f; lreg[i] = 0.f;
#pragma unroll
        for (int c = 0; c < 4; c++) o[i][c] = 0.f;
    }

    for (int s0 = 0; s0 < NS; s0 += 64) {
#pragma unroll
        for (int it = 0; it < 4; it++) {
            int i = tid + it * 256;
            int n = i >> 4, d4 = (i & 15) * 4;
            float4 kv, vv;
            if (s0 + n < NS) {
                kv = *(const float4*)(Kp + (size_t)(s0 + n)*ND + d4);
                vv = *(const float4*)(Vp + (size_t)(s0 + n)*ND + d4);
            } else {
                kv = make_float4(0.f,0.f,0.f,0.f);
                vv = make_float4(0.f,0.f,0.f,0.f);
            }
            Ks[n*65 + d4 + 0] = kv.x;
            Ks[n*65 + d4 + 1] = kv.y;
            Ks[n*65 + d4 + 2] = kv.z;
            Ks[n*65 + d4 + 3] = kv.w;
            *(float4*)&Vs[n*64 + d4] = vv;
        }
        __syncthreads();

        float sacc[4][4];
#pragma unroll
        for (int i = 0; i < 4; i++)
#pragma unroll
            for (int j = 0; j < 4; j++) sacc[i][j] = 0.f;
#pragma unroll 8
        for (int d = 0; d < 64; d++) {
            float qa[4], kb[4];
#pragma unroll
            for (int i = 0; i < 4; i++) qa[i] = Qs[(ty*4+i)*65 + d];
#pragma unroll
            for (int j = 0; j < 4; j++) kb[j] = Ks[(tx*4+j)*65 + d];
#pragma unroll
            for (int i = 0; i < 4; i++)
#pragma unroll
                for (int j = 0; j < 4; j++)
                    sacc[i][j] = fmaf(qa[i], kb[j], sacc[i][j]);
        }
        if (s0 + 64 > NS) {
#pragma unroll
            for (int j = 0; j < 4; j++)
                if (s0 + tx*4 + j >= NS) {
#pragma unroll
                    for (int i = 0; i < 4; i++) sacc[i][j] = -1e30f;
                }
        }
        __syncthreads();

        float p[4][4];
#pragma unroll
        for (int i = 0; i < 4; i++) {
            float rmax = fmaxf(fmaxf(sacc[i][0], sacc[i][1]),
                               fmaxf(sacc[i][2], sacc[i][3]));
#pragma unroll
            for (int off = 8; off >= 1; off >>= 1)
                rmax = fmaxf(rmax, __shfl_xor_sync(0xffffffffu, rmax, off, 16));
            float mnew = fmaxf(mreg[i], rmax);
            float alpha = __expf(mreg[i] - mnew);
            float ps = 0.f;
#pragma unroll
            for (int j = 0; j < 4; j++) {
                p[i][j] = __expf(sacc[i][j] - mnew);
                ps += p[i][j];
            }
#pragma unroll
            for (int off = 8; off >= 1; off >>= 1)
                ps += __shfl_xor_sync(0xffffffffu, ps, off, 16);
            lreg[i] = lreg[i]*alpha + ps;
            mreg[i] = mnew;
#pragma unroll
            for (int c = 0; c < 4; c++) o[i][c] *= alpha;
        }
#pragma unroll
        for (int i = 0; i < 4; i++)
            *(float4*)&Ks[(ty*4+i)*64 + tx*4] = *(float4*)p[i];
        __syncthreads();

#pragma unroll 8
        for (int j = 0; j < 64; j++) {
            float pv0[4], vb[4];
#pragma unroll
            for (int i = 0; i < 4; i++) pv0[i] = Ks[(ty*4+i)*64 + j];
            *(float4*)vb = *(const float4*)&Vs[j*64 + tx*4];
#pragma unroll
            for (int i = 0; i < 4; i++)
#pragma unroll
                for (int c = 0; c < 4; c++)
                    o[i][c] = fmaf(pv0[i], vb[c], o[i][c]);
        }
        __syncthreads();
    }

#pragma unroll
    for (int i = 0; i < 4; i++) {
        float inv = 1.f / lreg[i];
        int t = q0 + ty*4 + i;
        float v[4];
#pragma unroll
        for (int c = 0; c < 4; c++) v[c] = o[i][c] * inv;
        *(float4*)&g_att[((size_t)(b*NT + t))*NC + h*ND + tx*4] = *(float4*)v;
    }
}

// ---------------------------------------------------------------------------
// Launch: weight prep -> prefix fill -> QKV mma-GEMM -> attention -> out GEMM
// ---------------------------------------------------------------------------
extern "C" void kernel_launch(void* const* d_in, const int* in_sizes, int n_in,
                              void* d_out, int out_size) {
    const float* x    = (const float*)d_in[0];
    const float* pk   = (const float*)d_in[1];
    const float* pv   = (const float*)d_in[2];
    const float* Wqkv = (const float*)d_in[3];
    const float* bqkv = (const float*)d_in[4];
    const float* Wout = (const float*)d_in[5];
    const float* bout = (const float*)d_in[6];
    float* out = (float*)d_out;

    cudaFuncSetAttribute(attn_kernel,
                         cudaFuncAttributeMaxDynamicSharedMemorySize, ATTN_SMEM);
    cudaFuncSetAttribute(mma_gemm_kernel<0>,
                         cudaFuncAttributeMaxDynamicSharedMemorySize, GEMM_SMEM);
    cudaFuncSetAttribute(mma_gemm_kernel<1>,
                         cudaFuncAttributeMaxDynamicSharedMemorySize, GEMM_SMEM);

    unsigned short *wqh, *wql, *woh, *wol;
    cudaGetSymbolAddress((void**)&wqh, g_wqkv_h);
    cudaGetSymbolAddress((void**)&wql, g_wqkv_l);
    cudaGetSymbolAddress((void**)&woh, g_wout_h);
    cudaGetSymbolAddress((void**)&wol, g_wout_l);

    dim3 tb(32, 8);
    wprep_kernel<<<dim3(96, 32), tb>>>(Wqkv, 3*NC, wqh, wql);
    wprep_kernel<<<dim3(32, 32), tb>>>(Wout,   NC, woh, wol);
    prefix_fill_kernel<<<64, 256>>>(pk, pv);

    mma_gemm_kernel<0><<<dim3(24, 32), 256, GEMM_SMEM>>>(x, bqkv, nullptr);
    attn_kernel<<<dim3(32, 32), 256, ATTN_SMEM>>>();
    mma_gemm_kernel<1><<<dim3(8, 32), 256, GEMM_SMEM>>>(nullptr, bout, out);
}

// round 6
// speedup vs baseline: 3.1695x; 2.3355x over previous
#include <cuda_runtime.h>
#include <cuda_bf16.h>
#include <cuda_fp16.h>
#include <cstdint>

// Problem constants
#define NB 2
#define NT 2048
#define NC 1024
#define NH 16
#define ND 64
#define NP 16
#define NS 2064      // NP + NT
#define SPAD 2112    // 33 chunks of 64
#define NROWS 4096   // NB * NT

// ---------------------------------------------------------------------------
// Scratch (allocation-free: __device__ globals). Packed-pair u32 arrays.
// ---------------------------------------------------------------------------
__device__ float g_att[(size_t)NROWS*NC];            // [b,t, h*64+d] fp32
__device__ uint32_t g_qh[NB*NH*NT*ND/2];             // bf16x2 [bh][t][d/2] (q*0.125 hi)
__device__ uint32_t g_ql[NB*NH*NT*ND/2];             // lo residual
__device__ uint32_t g_kh[NB*NH*SPAD*ND/2];           // bf16x2 [bh][s][d/2]
__device__ uint32_t g_kl[NB*NH*SPAD*ND/2];
__device__ uint32_t g_vh[NB*NH*SPAD*ND/2];           // fp16x2
// Pre-transposed + hi/lo-split weights, [N][K=1024] bf16
__device__ unsigned short g_wqkv_h[3*NC*NC];
__device__ unsigned short g_wqkv_l[3*NC*NC];
__device__ unsigned short g_wout_h[NC*NC];
__device__ unsigned short g_wout_l[NC*NC];

// ---------------------------------------------------------------------------
// Helpers (family-agnostic: ldmatrix / mma.sync / cp.async only)
// ---------------------------------------------------------------------------
__device__ __forceinline__ uint32_t smem_u32(const void* p) {
    uint32_t a;
    asm("{ .reg .u64 t; cvta.to.shared.u64 t, %1; cvt.u32.u64 %0, t; }" : "=r"(a) : "l"(p));
    return a;
}

#define STS128(addr, a, b, c, d) \
    asm volatile("st.shared.v4.b32 [%0], {%1,%2,%3,%4};" :: "r"(addr), "r"(a), "r"(b), "r"(c), "r"(d) : "memory")

#define CP_ASYNC16(dst, src) \
    asm volatile("cp.async.cg.shared.global [%0], [%1], 16;" :: "r"(dst), "l"(src) : "memory")
#define CP_COMMIT() asm volatile("cp.async.commit_group;" ::: "memory")
#define CP_WAIT0()  asm volatile("cp.async.wait_group 0;" ::: "memory")
#define CP_WAIT1()  asm volatile("cp.async.wait_group 1;" ::: "memory")

#define SW128(o) ((o) ^ (((o) >> 3) & 0x70))
__device__ __forceinline__ uint32_t swz(uint32_t base, uint32_t off) {
    return base + SW128(off);
}

__device__ __forceinline__ void ldsm_x4(uint32_t& r0, uint32_t& r1, uint32_t& r2, uint32_t& r3,
                                        uint32_t addr) {
    asm volatile("ldmatrix.sync.aligned.m8n8.x4.shared.b16 {%0,%1,%2,%3}, [%4];"
                 : "=r"(r0), "=r"(r1), "=r"(r2), "=r"(r3) : "r"(addr));
}
__device__ __forceinline__ void ldsm_x4t(uint32_t& r0, uint32_t& r1, uint32_t& r2, uint32_t& r3,
                                         uint32_t addr) {
    asm volatile("ldmatrix.sync.aligned.m8n8.x4.trans.shared.b16 {%0,%1,%2,%3}, [%4];"
                 : "=r"(r0), "=r"(r1), "=r"(r2), "=r"(r3) : "r"(addr));
}

__device__ __forceinline__ void mma_bf16(float* d, const uint32_t* a, const uint32_t* b) {
    asm volatile("mma.sync.aligned.m16n8k16.row.col.f32.bf16.bf16.f32 "
                 "{%0,%1,%2,%3}, {%4,%5,%6,%7}, {%8,%9}, {%0,%1,%2,%3};"
                 : "+f"(d[0]), "+f"(d[1]), "+f"(d[2]), "+f"(d[3])
                 : "r"(a[0]), "r"(a[1]), "r"(a[2]), "r"(a[3]), "r"(b[0]), "r"(b[1]));
}
__device__ __forceinline__ void mma_f16(float* d, const uint32_t* a, const uint32_t* b) {
    asm volatile("mma.sync.aligned.m16n8k16.row.col.f32.f16.f16.f32 "
                 "{%0,%1,%2,%3}, {%4,%5,%6,%7}, {%8,%9}, {%0,%1,%2,%3};"
                 : "+f"(d[0]), "+f"(d[1]), "+f"(d[2]), "+f"(d[3])
                 : "r"(a[0]), "r"(a[1]), "r"(a[2]), "r"(a[3]), "r"(b[0]), "r"(b[1]));
}

// hi/lo bf16 split of two floats packed into two u32
__device__ __forceinline__ void cvt2(float a, float b, uint32_t& h, uint32_t& l) {
    __nv_bfloat16 ha = __float2bfloat16_rn(a);
    __nv_bfloat16 hb = __float2bfloat16_rn(b);
    __nv_bfloat16 la = __float2bfloat16_rn(a - __bfloat162float(ha));
    __nv_bfloat16 lb = __float2bfloat16_rn(b - __bfloat162float(hb));
    h = ((uint32_t)__bfloat16_as_ushort(hb) << 16) | (uint32_t)__bfloat16_as_ushort(ha);
    l = ((uint32_t)__bfloat16_as_ushort(lb) << 16) | (uint32_t)__bfloat16_as_ushort(la);
}
__device__ __forceinline__ uint32_t h2pack(float a, float b) {
    __half2 h = __floats2half2_rn(a, b);
    return *reinterpret_cast<uint32_t*>(&h);
}

// ---------------------------------------------------------------------------
// Weight prep: W [K=1024][N] fp32 -> Wt_h/Wt_l [N][1024] bf16 (hi/lo split)
// ---------------------------------------------------------------------------
__global__ void wprep_kernel(const float* __restrict__ W, int N,
                             unsigned short* __restrict__ Wt_h,
                             unsigned short* __restrict__ Wt_l) {
    __shared__ float tile[32][33];
    const int n0 = blockIdx.x * 32, k0 = blockIdx.y * 32;
    const int tx = threadIdx.x, ty = threadIdx.y;  // 32 x 8
#pragma unroll
    for (int i = 0; i < 32; i += 8)
        tile[ty + i][tx] = W[(size_t)(k0 + ty + i) * N + n0 + tx];
    __syncthreads();
#pragma unroll
    for (int i = 0; i < 32; i += 8) {
        float v = tile[tx][ty + i];
        __nv_bfloat16 h = __float2bfloat16_rn(v);
        __nv_bfloat16 l = __float2bfloat16_rn(v - __bfloat162float(h));
        size_t o = (size_t)(n0 + ty + i) * NC + k0 + tx;
        Wt_h[o] = __bfloat16_as_ushort(h);
        Wt_l[o] = __bfloat16_as_ushort(l);
    }
}

// ---------------------------------------------------------------------------
// Prefix: convert prefix_k/v fp32 -> split bf16 K / fp16 V rows 0..15 (both b);
// zero-fill pad rows 2064..2111.
// ---------------------------------------------------------------------------
__global__ void prefix_fill_kernel(const float* __restrict__ pk,
                                   const float* __restrict__ pv) {
    int idx = blockIdx.x * blockDim.x + threadIdx.x;
    if (idx < NH*NP*32) {                 // pair-granularity prefix fill
        int h = idx >> 9;
        int p = (idx >> 5) & (NP - 1);
        int dp = idx & 31;
        const float* kp = pk + ((size_t)h * NP + p) * ND + 2*dp;
        const float* vp = pv + ((size_t)h * NP + p) * ND + 2*dp;
        uint32_t kh, kl;
        cvt2(kp[0], kp[1], kh, kl);
        uint32_t vh = h2pack(vp[0], vp[1]);
#pragma unroll
        for (int b = 0; b < NB; b++) {
            size_t o = ((size_t)(b*NH + h) * SPAD + p) * 32 + dp;
            g_kh[o] = kh; g_kl[o] = kl; g_vh[o] = vh;
        }
    } else {
        int j = idx - NH*NP*32;
        if (j < NB*NH*48*32) {            // pad rows 2064..2111
            int bh = j / (48*32);
            int rem = j % (48*32);
            int r = NS + (rem >> 5);
            int dp = rem & 31;
            size_t o = ((size_t)bh * SPAD + r) * 32 + dp;
            g_kh[o] = 0; g_kl[o] = 0; g_vh[o] = 0;
        }
    }
}

// ---------------------------------------------------------------------------
// mma.sync GEMM (as R5): C[M,N] = A[M,1024] @ Wt^T with 3-term bf16 split.
// MODE 0: A = x; epilogue writes split-bf16 q (x0.125) / k and fp16 v.
// MODE 1: A = g_att; epilogue adds bias, writes d_out fp32.
// ---------------------------------------------------------------------------
#define GEMM_SMEM (2*65536 + 1024)
#define NCH 16

template<int MODE>
__global__ __launch_bounds__(256) void mma_gemm_kernel(const float* __restrict__ A,
                                                       const float* __restrict__ bias,
                                                       float* __restrict__ out) {
    extern __shared__ char dsm[];
    const uint32_t sb = (smem_u32(dsm) + 1023u) & ~1023u;

    const int tid = threadIdx.x;
    const int lane = tid & 31;
    const int wm = (tid >> 5) & 3;
    const int wn = tid >> 7;
    const int r0 = blockIdx.y * 128;
    const int c0 = blockIdx.x * 128;

    const float* Ap = (MODE == 0) ? A : g_att;
    const unsigned short* Wh = (MODE == 0) ? g_wqkv_h : g_wout_h;
    const unsigned short* Wl = (MODE == 0) ? g_wqkv_l : g_wout_l;

    const uint32_t a_off = (uint32_t)((32*wm + (lane & 15)) * 128 + (lane >> 4) * 16);
    const uint32_t b_off = (uint32_t)((64*wn + ((lane >> 4) & 1) * 8 + (lane & 7)) * 128
                                      + ((lane >> 3) & 1) * 16);
    const int ldrow = tid >> 3;
    const int ldc8  = (tid & 7) * 8;

    float acc[2][8][4];
#pragma unroll
    for (int mf = 0; mf < 2; mf++)
#pragma unroll
        for (int ng = 0; ng < 8; ng++)
#pragma unroll
            for (int c = 0; c < 4; c++) acc[mf][ng][c] = 0.f;

    float4 av[4][2];

    auto loadB = [&](int ch, uint32_t bb) {
#pragma unroll
        for (int it = 0; it < 4; ++it) {
            int n  = ldrow + it * 32;
            size_t go = (size_t)(c0 + n) * NC + ch * 64 + ldc8;
            uint32_t off = SW128((uint32_t)(n * 128 + ldc8 * 2));
            CP_ASYNC16(bb + 32768u + off, Wh + go);
            CP_ASYNC16(bb + 49152u + off, Wl + go);
        }
    };
    auto loadA = [&](int ch) {
#pragma unroll
        for (int it = 0; it < 4; ++it) {
            int row = ldrow + it * 32;
            const float* ap = Ap + (size_t)(r0 + row) * NC + ch * 64 + ldc8;
            av[it][0] = *(const float4*)ap;
            av[it][1] = *(const float4*)(ap + 4);
        }
    };
    auto stsA = [&](uint32_t bb) {
#pragma unroll
        for (int it = 0; it < 4; ++it) {
            int row = ldrow + it * 32;
            uint32_t h[4], l[4];
            cvt2(av[it][0].x, av[it][0].y, h[0], l[0]);
            cvt2(av[it][0].z, av[it][0].w, h[1], l[1]);
            cvt2(av[it][1].x, av[it][1].y, h[2], l[2]);
            cvt2(av[it][1].z, av[it][1].w, h[3], l[3]);
            uint32_t off = SW128((uint32_t)(row * 128 + ldc8 * 2));
            STS128(bb + off,          h[0], h[1], h[2], h[3]);
            STS128(bb + 16384u + off, l[0], l[1], l[2], l[3]);
        }
    };

    loadB(0, sb);
    CP_COMMIT();
    loadA(0);
    stsA(sb);
    CP_WAIT0();
    __syncthreads();

    for (int ch = 0; ch < NCH; ++ch) {
        const uint32_t base = sb + (uint32_t)(ch & 1) * 65536u;
        const uint32_t nbase = sb + (uint32_t)((ch & 1) ^ 1) * 65536u;

        if (ch + 1 < NCH) {
            loadB(ch + 1, nbase);
            CP_COMMIT();
            loadA(ch + 1);
        }

        const uint32_t bAh = base, bAl = base + 16384u;
        const uint32_t bBh = base + 32768u, bBl = base + 49152u;
#pragma unroll
        for (int kk = 0; kk < 4; ++kk) {
            uint32_t Ah[2][4], Al[2][4];
#pragma unroll
            for (int mf = 0; mf < 2; mf++) {
                uint32_t o = a_off + kk * 32 + mf * 2048;
                ldsm_x4(Ah[mf][0], Ah[mf][1], Ah[mf][2], Ah[mf][3], swz(bAh, o));
                ldsm_x4(Al[mf][0], Al[mf][1], Al[mf][2], Al[mf][3], swz(bAl, o));
            }
#pragma unroll
            for (int g = 0; g < 4; ++g) {
                uint32_t Bh[4], Bl[4];
                uint32_t o = b_off + g * 2048 + kk * 32;
                ldsm_x4(Bh[0], Bh[1], Bh[2], Bh[3], swz(bBh, o));
                ldsm_x4(Bl[0], Bl[1], Bl[2], Bl[3], swz(bBl, o));
#pragma unroll
                for (int mf = 0; mf < 2; mf++) {
                    mma_bf16(acc[mf][2*g],   Ah[mf], Bh);
                    mma_bf16(acc[mf][2*g+1], Ah[mf], Bh + 2);
                }
#pragma unroll
                for (int mf = 0; mf < 2; mf++) {
                    mma_bf16(acc[mf][2*g],   Al[mf], Bh);
                    mma_bf16(acc[mf][2*g+1], Al[mf], Bh + 2);
                }
#pragma unroll
                for (int mf = 0; mf < 2; mf++) {
                    mma_bf16(acc[mf][2*g],   Ah[mf], Bl);
                    mma_bf16(acc[mf][2*g+1], Ah[mf], Bl + 2);
                }
            }
        }

        if (ch + 1 < NCH) {
            stsA(nbase);
            CP_WAIT0();
            __syncthreads();
        }
    }

    // ---- epilogue ----
    const int g4 = lane >> 2, t4 = lane & 3;
    const int colb = c0 + 64 * wn;
    const int which = colb >> 10;               // MODE 0 only
    const int hh = (colb >> 6) & (NH - 1);
#pragma unroll
    for (int ng = 0; ng < 8; ++ng) {
        const int col = colb + 8 * ng + 2 * t4;
        const float b0v = bias[col], b1v = bias[col + 1];
#pragma unroll
        for (int mf = 0; mf < 2; mf++) {
            const int row = r0 + 32 * wm + 16 * mf + g4;
            const float* ac = acc[mf][ng];
            if (MODE == 1) {
                float2 v0 = make_float2(ac[0] + b0v, ac[1] + b1v);
                float2 v1 = make_float2(ac[2] + b0v, ac[3] + b1v);
                *(float2*)&out[(size_t)row * NC + col] = v0;
                *(float2*)&out[(size_t)(row + 8) * NC + col] = v1;
            } else {
                const int dp = 4*ng + t4;       // d-pair index 0..31
#pragma unroll
                for (int rr = 0; rr < 2; rr++) {
                    const int r = row + 8*rr;
                    const int b = r >> 11, t = r & (NT - 1);
                    const int bh = b * NH + hh;
                    float x = ac[2*rr] + b0v, y = ac[2*rr+1] + b1v;
                    if (which == 0) {
                        uint32_t h, l;
                        cvt2(x * 0.125f, y * 0.125f, h, l);
                        size_t o = ((size_t)bh * NT + t) * 32 + dp;
                        g_qh[o] = h; g_ql[o] = l;
                    } else if (which == 1) {
                        uint32_t h, l;
                        cvt2(x, y, h, l);
                        size_t o = ((size_t)bh * SPAD + NP + t) * 32 + dp;
                        g_kh[o] = h; g_kl[o] = l;
                    } else {
                        size_t o = ((size_t)bh * SPAD + NP + t) * 32 + dp;
                        g_vh[o] = h2pack(x, y);
                    }
                }
            }
        }
    }
}

// ---------------------------------------------------------------------------
// Tensor-core flash attention.
// CTA: 128 queries x one (b,h); 8 warps x 16 rows. S chunks of 64.
// QK^T: 3-term bf16 split. Softmax fp32. PV: fp16 single-pass.
// smem: Qh 16K | Ql 16K | 2 x (Kh 8K | Kl 8K | V 8K) = 80K.
// ---------------------------------------------------------------------------
#define ATTN_SMEM (16384*2 + 2*24576 + 1024)
#define NCHUNK 33

__global__ __launch_bounds__(256, 2) void attn_kernel() {
    extern __shared__ char dsm[];
    const uint32_t sb  = (smem_u32(dsm) + 1023u) & ~1023u;
    const uint32_t sQh = sb, sQl = sb + 16384u;
    const uint32_t sBuf0 = sb + 32768u;       // each buf: Kh | Kl | V (8K each)

    const int bh = blockIdx.y;
    const int q0 = blockIdx.x * 128;
    const int b = bh >> 4, h = bh & (NH - 1);
    const int tid = threadIdx.x;
    const int lane = tid & 31;
    const int wid = tid >> 5;

    const uint32_t* Qhp = g_qh + ((size_t)bh * NT + q0) * 32;
    const uint32_t* Qlp = g_ql + ((size_t)bh * NT + q0) * 32;
    const uint32_t* Khp = g_kh + (size_t)bh * SPAD * 32;
    const uint32_t* Klp = g_kl + (size_t)bh * SPAD * 32;
    const uint32_t* Vhp = g_vh + (size_t)bh * SPAD * 32;

    // ldmatrix lane offsets
    const uint32_t a_off = (uint32_t)((16*wid + (lane & 15)) * 128 + (lane >> 4) * 16);
    const uint32_t b_off = (uint32_t)((((lane >> 4) & 1) * 8 + (lane & 7)) * 128
                                      + ((lane >> 3) & 1) * 16);
    const uint32_t v_off = (uint32_t)((lane & 15) * 128 + (lane >> 4) * 16);

    // ---- Q load (once) ----
#pragma unroll
    for (int it = 0; it < 8; ++it) {
        int idx = tid + it * 256;               // 0..2047
        int ten = idx >> 10;                    // 0 = Qh, 1 = Ql
        int r = (idx & 1023) >> 3;
        int seg = idx & 7;
        const uint32_t* src = (ten ? Qlp : Qhp) + (size_t)r * 32 + seg * 4;
        uint32_t dst = (ten ? sQl : sQh) + SW128((uint32_t)(r * 128 + seg * 16));
        CP_ASYNC16(dst, src);
    }
    // chunk loader
    auto loadChunk = [&](int ci, uint32_t bb) {
#pragma unroll
        for (int it = 0; it < 6; ++it) {
            int idx = tid + it * 256;           // 0..1535
            int ten = idx / 512;                // 0 Kh, 1 Kl, 2 V
            int r = (idx & 511) >> 3;
            int seg = idx & 7;
            const uint32_t* base = (ten == 0) ? Khp : (ten == 1) ? Klp : Vhp;
            const uint32_t* src = base + (size_t)(ci * 64 + r) * 32 + seg * 4;
            uint32_t dst = bb + (uint32_t)ten * 8192u + SW128((uint32_t)(r * 128 + seg * 16));
            CP_ASYNC16(dst, src);
        }
    };
    loadChunk(0, sBuf0);
    CP_COMMIT();

    float O[8][4];
#pragma unroll
    for (int g = 0; g < 8; g++)
#pragma unroll
        for (int c = 0; c < 4; c++) O[g][c] = 0.f;
    float m0 = -1e30f, m1 = -1e30f, l0 = 0.f, l1 = 0.f;

    for (int ci = 0; ci < NCHUNK; ++ci) {
        const uint32_t buf  = sBuf0 + (uint32_t)(ci & 1) * 24576u;
        const uint32_t nbuf = sBuf0 + (uint32_t)((ci & 1) ^ 1) * 24576u;
        if (ci + 1 < NCHUNK) {
            loadChunk(ci + 1, nbuf);
            CP_COMMIT();
            CP_WAIT1();
        } else {
            CP_WAIT0();
        }
        __syncthreads();

        const uint32_t bKh = buf, bKl = buf + 8192u, bV = buf + 16384u;

        // ---- S = Q K^T (3-term split) ----
        float S[8][4];
#pragma unroll
        for (int g = 0; g < 8; g++)
#pragma unroll
            for (int c = 0; c < 4; c++) S[g][c] = 0.f;
#pragma unroll
        for (int kk = 0; kk < 4; ++kk) {
            uint32_t Ah[4], Al[4];
            ldsm_x4(Ah[0], Ah[1], Ah[2], Ah[3], swz(sQh, a_off + kk * 32));
            ldsm_x4(Al[0], Al[1], Al[2], Al[3], swz(sQl, a_off + kk * 32));
#pragma unroll
            for (int gg = 0; gg < 4; ++gg) {
                uint32_t Kh[4], Kl[4];
                uint32_t o = b_off + gg * 2048 + kk * 32;
                ldsm_x4(Kh[0], Kh[1], Kh[2], Kh[3], swz(bKh, o));
                ldsm_x4(Kl[0], Kl[1], Kl[2], Kl[3], swz(bKl, o));
                mma_bf16(S[2*gg],   Ah, Kh);  mma_bf16(S[2*gg+1], Ah, Kh + 2);
                mma_bf16(S[2*gg],   Al, Kh);  mma_bf16(S[2*gg+1], Al, Kh + 2);
                mma_bf16(S[2*gg],   Ah, Kl);  mma_bf16(S[2*gg+1], Ah, Kl + 2);
            }
        }

        // ---- tail mask (chunk 32: only cols 0..15 valid => frags g>=2) ----
        if (ci == NCHUNK - 1) {
#pragma unroll
            for (int g = 2; g < 8; g++)
#pragma unroll
                for (int c = 0; c < 4; c++) S[g][c] = -1e30f;
        }

        // ---- online softmax (rows r = lane>>2 and r+8) ----
        float tm0 = -1e30f, tm1 = -1e30f;
#pragma unroll
        for (int g = 0; g < 8; g++) {
            tm0 = fmaxf(tm0, fmaxf(S[g][0], S[g][1]));
            tm1 = fmaxf(tm1, fmaxf(S[g][2], S[g][3]));
        }
        tm0 = fmaxf(tm0, __shfl_xor_sync(0xffffffffu, tm0, 1));
        tm0 = fmaxf(tm0, __shfl_xor_sync(0xffffffffu, tm0, 2));
        tm1 = fmaxf(tm1, __shfl_xor_sync(0xffffffffu, tm1, 1));
        tm1 = fmaxf(tm1, __shfl_xor_sync(0xffffffffu, tm1, 2));
        float mn0 = fmaxf(m0, tm0), mn1 = fmaxf(m1, tm1);
        float al0 = __expf(m0 - mn0), al1 = __expf(m1 - mn1);
        float s0 = 0.f, s1 = 0.f;
#pragma unroll
        for (int g = 0; g < 8; g++) {
            S[g][0] = __expf(S[g][0] - mn0);
            S[g][1] = __expf(S[g][1] - mn0);
            S[g][2] = __expf(S[g][2] - mn1);
            S[g][3] = __expf(S[g][3] - mn1);
            s0 += S[g][0] + S[g][1];
            s1 += S[g][2] + S[g][3];
        }
        s0 += __shfl_xor_sync(0xffffffffu, s0, 1);
        s0 += __shfl_xor_sync(0xffffffffu, s0, 2);
        s1 += __shfl_xor_sync(0xffffffffu, s1, 1);
        s1 += __shfl_xor_sync(0xffffffffu, s1, 2);
        l0 = l0 * al0 + s0; l1 = l1 * al1 + s1;
        m0 = mn0; m1 = mn1;
#pragma unroll
        for (int g = 0; g < 8; g++) {
            O[g][0] *= al0; O[g][1] *= al0;
            O[g][2] *= al1; O[g][3] *= al1;
        }

        // ---- pack P to fp16 A-frags ----
        uint32_t pa[4][4];
#pragma unroll
        for (int kk = 0; kk < 4; ++kk) {
            pa[kk][0] = h2pack(S[2*kk][0],   S[2*kk][1]);
            pa[kk][1] = h2pack(S[2*kk][2],   S[2*kk][3]);
            pa[kk][2] = h2pack(S[2*kk+1][0], S[2*kk+1][1]);
            pa[kk][3] = h2pack(S[2*kk+1][2], S[2*kk+1][3]);
        }

        // ---- O += P V ----
#pragma unroll
        for (int kk = 0; kk < 4; ++kk) {
#pragma unroll
            for (int gg = 0; gg < 4; ++gg) {
                uint32_t Vb[4];
                uint32_t o = v_off + kk * 2048 + gg * 32;
                ldsm_x4t(Vb[0], Vb[1], Vb[2], Vb[3], swz(bV, o));
                mma_f16(O[2*gg],   pa[kk], Vb);
                mma_f16(O[2*gg+1], pa[kk], Vb + 2);
            }
        }
        __syncthreads();
    }

    // ---- epilogue: normalize, write g_att [b,t, h*64+d] ----
    const float inv0 = 1.f / l0, inv1 = 1.f / l1;
    const int r = lane >> 2;
    const int row0 = q0 + 16*wid + r;
#pragma unroll
    for (int g = 0; g < 8; g++) {
        const int d = h * ND + 8*g + 2*(lane & 3);
        float2 v0 = make_float2(O[g][0] * inv0, O[g][1] * inv0);
        float2 v1 = make_float2(O[g][2] * inv1, O[g][3] * inv1);
        *(float2*)&g_att[((size_t)(b*NT + row0))*NC + d] = v0;
        *(float2*)&g_att[((size_t)(b*NT + row0 + 8))*NC + d] = v1;
    }
}

// ---------------------------------------------------------------------------
// Launch
// ---------------------------------------------------------------------------
extern "C" void kernel_launch(void* const* d_in, const int* in_sizes, int n_in,
                              void* d_out, int out_size) {
    const float* x    = (const float*)d_in[0];
    const float* pk   = (const float*)d_in[1];
    const float* pv   = (const float*)d_in[2];
    const float* Wqkv = (const float*)d_in[3];
    const float* bqkv = (const float*)d_in[4];
    const float* Wout = (const float*)d_in[5];
    const float* bout = (const float*)d_in[6];
    float* out = (float*)d_out;

    cudaFuncSetAttribute(attn_kernel,
                         cudaFuncAttributeMaxDynamicSharedMemorySize, ATTN_SMEM);
    cudaFuncSetAttribute(mma_gemm_kernel<0>,
                         cudaFuncAttributeMaxDynamicSharedMemorySize, GEMM_SMEM);
    cudaFuncSetAttribute(mma_gemm_kernel<1>,
                         cudaFuncAttributeMaxDynamicSharedMemorySize, GEMM_SMEM);

    unsigned short *wqh, *wql, *woh, *wol;
    cudaGetSymbolAddress((void**)&wqh, g_wqkv_h);
    cudaGetSymbolAddress((void**)&wql, g_wqkv_l);
    cudaGetSymbolAddress((void**)&woh, g_wout_h);
    cudaGetSymbolAddress((void**)&wol, g_wout_l);

    dim3 tb(32, 8);
    wprep_kernel<<<dim3(96, 32), tb>>>(Wqkv, 3*NC, wqh, wql);
    wprep_kernel<<<dim3(32, 32), tb>>>(Wout,   NC, woh, wol);
    prefix_fill_kernel<<<224, 256>>>(pk, pv);

    mma_gemm_kernel<0><<<dim3(24, 32), 256, GEMM_SMEM>>>(x, bqkv, nullptr);
    attn_kernel<<<dim3(16, 32), 256, ATTN_SMEM>>>();
    mma_gemm_kernel<1><<<dim3(8, 32), 256, GEMM_SMEM>>>(nullptr, bout, out);
}

// round 8
// speedup vs baseline: 3.5799x; 1.1295x over previous
#include <cuda_runtime.h>
#include <cuda_bf16.h>
#include <cuda_fp16.h>
#include <cstdint>

// Problem constants
#define NB 2
#define NT 2048
#define NC 1024
#define NH 16
#define ND 64
#define NP 16
#define NS 2064      // NP + NT
#define SPAD 2112    // 33 chunks of 64
#define NROWS 4096   // NB * NT

// ---------------------------------------------------------------------------
// Scratch (allocation-free: __device__ globals). Packed-pair u32 arrays.
// ---------------------------------------------------------------------------
__device__ uint32_t g_xh[(size_t)NROWS*NC/2];        // x split hi, [row][512] bf16x2
__device__ uint32_t g_xl[(size_t)NROWS*NC/2];
__device__ uint32_t g_ath[(size_t)NROWS*NC/2];       // attention out split hi
__device__ uint32_t g_atl[(size_t)NROWS*NC/2];
__device__ uint32_t g_qh[NB*NH*NT*ND/2];             // bf16x2 [bh][t][d/2] (q*0.125)
__device__ uint32_t g_ql[NB*NH*NT*ND/2];
__device__ uint32_t g_kh[NB*NH*SPAD*ND/2];           // bf16x2 [bh][s][d/2]
__device__ uint32_t g_kl[NB*NH*SPAD*ND/2];
__device__ uint32_t g_vh[NB*NH*SPAD*ND/2];           // fp16x2
// Pre-transposed + hi/lo-split weights, [N][K=1024] bf16
__device__ unsigned short g_wqkv_h[3*NC*NC];
__device__ unsigned short g_wqkv_l[3*NC*NC];
__device__ unsigned short g_wout_h[NC*NC];
__device__ unsigned short g_wout_l[NC*NC];

// ---------------------------------------------------------------------------
// Helpers (family-agnostic: ldmatrix / mma.sync / cp.async only)
// ---------------------------------------------------------------------------
__device__ __forceinline__ uint32_t smem_u32(const void* p) {
    uint32_t a;
    asm("{ .reg .u64 t; cvta.to.shared.u64 t, %1; cvt.u32.u64 %0, t; }" : "=r"(a) : "l"(p));
    return a;
}

#define CP_ASYNC16(dst, src) \
    asm volatile("cp.async.cg.shared.global [%0], [%1], 16;" :: "r"(dst), "l"(src) : "memory")
#define CP_COMMIT() asm volatile("cp.async.commit_group;" ::: "memory")
#define CP_WAIT0()  asm volatile("cp.async.wait_group 0;" ::: "memory")
#define CP_WAIT1()  asm volatile("cp.async.wait_group 1;" ::: "memory")

#define SW128(o) ((o) ^ (((o) >> 3) & 0x70))
__device__ __forceinline__ uint32_t swz(uint32_t base, uint32_t off) {
    return base + SW128(off);
}

__device__ __forceinline__ void ldsm_x4(uint32_t& r0, uint32_t& r1, uint32_t& r2, uint32_t& r3,
                                        uint32_t addr) {
    asm volatile("ldmatrix.sync.aligned.m8n8.x4.shared.b16 {%0,%1,%2,%3}, [%4];"
                 : "=r"(r0), "=r"(r1), "=r"(r2), "=r"(r3) : "r"(addr));
}
__device__ __forceinline__ void ldsm_x4t(uint32_t& r0, uint32_t& r1, uint32_t& r2, uint32_t& r3,
                                         uint32_t addr) {
    asm volatile("ldmatrix.sync.aligned.m8n8.x4.trans.shared.b16 {%0,%1,%2,%3}, [%4];"
                 : "=r"(r0), "=r"(r1), "=r"(r2), "=r"(r3) : "r"(addr));
}

__device__ __forceinline__ void mma_bf16(float* d, const uint32_t* a, const uint32_t* b) {
    asm volatile("mma.sync.aligned.m16n8k16.row.col.f32.bf16.bf16.f32 "
                 "{%0,%1,%2,%3}, {%4,%5,%6,%7}, {%8,%9}, {%0,%1,%2,%3};"
                 : "+f"(d[0]), "+f"(d[1]), "+f"(d[2]), "+f"(d[3])
                 : "r"(a[0]), "r"(a[1]), "r"(a[2]), "r"(a[3]), "r"(b[0]), "r"(b[1]));
}
__device__ __forceinline__ void mma_f16(float* d, const uint32_t* a, const uint32_t* b) {
    asm volatile("mma.sync.aligned.m16n8k16.row.col.f32.f16.f16.f32 "
                 "{%0,%1,%2,%3}, {%4,%5,%6,%7}, {%8,%9}, {%0,%1,%2,%3};"
                 : "+f"(d[0]), "+f"(d[1]), "+f"(d[2]), "+f"(d[3])
                 : "r"(a[0]), "r"(a[1]), "r"(a[2]), "r"(a[3]), "r"(b[0]), "r"(b[1]));
}

// hi/lo bf16 split of two floats packed into two u32
__device__ __forceinline__ void cvt2(float a, float b, uint32_t& h, uint32_t& l) {
    __nv_bfloat16 ha = __float2bfloat16_rn(a);
    __nv_bfloat16 hb = __float2bfloat16_rn(b);
    __nv_bfloat16 la = __float2bfloat16_rn(a - __bfloat162float(ha));
    __nv_bfloat16 lb = __float2bfloat16_rn(b - __bfloat162float(hb));
    h = ((uint32_t)__bfloat16_as_ushort(hb) << 16) | (uint32_t)__bfloat16_as_ushort(ha);
    l = ((uint32_t)__bfloat16_as_ushort(lb) << 16) | (uint32_t)__bfloat16_as_ushort(la);
}
__device__ __forceinline__ uint32_t h2pack(float a, float b) {
    __half2 h = __floats2half2_rn(a, b);
    return *reinterpret_cast<uint32_t*>(&h);
}

// ---------------------------------------------------------------------------
// x prep: fp32 [4096][1024] -> bf16 hi/lo packed pairs [4096][512]
// ---------------------------------------------------------------------------
__global__ void xprep_kernel(const float* __restrict__ x) {
    int idx = blockIdx.x * blockDim.x + threadIdx.x;   // pair index
    if (idx >= NROWS * (NC/2)) return;
    float2 v = *(const float2*)(x + 2 * (size_t)idx);
    uint32_t h, l;
    cvt2(v.x, v.y, h, l);
    g_xh[idx] = h;
    g_xl[idx] = l;
}

// ---------------------------------------------------------------------------
// Weight prep: W [K=1024][N] fp32 -> Wt_h/Wt_l [N][1024] bf16 (hi/lo split)
// ---------------------------------------------------------------------------
__global__ void wprep_kernel(const float* __restrict__ W, int N,
                             unsigned short* __restrict__ Wt_h,
                             unsigned short* __restrict__ Wt_l) {
    __shared__ float tile[32][33];
    const int n0 = blockIdx.x * 32, k0 = blockIdx.y * 32;
    const int tx = threadIdx.x, ty = threadIdx.y;  // 32 x 8
#pragma unroll
    for (int i = 0; i < 32; i += 8)
        tile[ty + i][tx] = W[(size_t)(k0 + ty + i) * N + n0 + tx];
    __syncthreads();
#pragma unroll
    for (int i = 0; i < 32; i += 8) {
        float v = tile[tx][ty + i];
        __nv_bfloat16 h = __float2bfloat16_rn(v);
        __nv_bfloat16 l = __float2bfloat16_rn(v - __bfloat162float(h));
        size_t o = (size_t)(n0 + ty + i) * NC + k0 + tx;
        Wt_h[o] = __bfloat16_as_ushort(h);
        Wt_l[o] = __bfloat16_as_ushort(l);
    }
}

// ---------------------------------------------------------------------------
// Prefix fill + K/V pad rows
// ---------------------------------------------------------------------------
__global__ void prefix_fill_kernel(const float* __restrict__ pk,
                                   const float* __restrict__ pv) {
    int idx = blockIdx.x * blockDim.x + threadIdx.x;
    if (idx < NH*NP*32) {
        int h = idx >> 9;
        int p = (idx >> 5) & (NP - 1);
        int dp = idx & 31;
        const float* kp = pk + ((size_t)h * NP + p) * ND + 2*dp;
        const float* vp = pv + ((size_t)h * NP + p) * ND + 2*dp;
        uint32_t kh, kl;
        cvt2(kp[0], kp[1], kh, kl);
        uint32_t vh = h2pack(vp[0], vp[1]);
#pragma unroll
        for (int b = 0; b < NB; b++) {
            size_t o = ((size_t)(b*NH + h) * SPAD + p) * 32 + dp;
            g_kh[o] = kh; g_kl[o] = kl; g_vh[o] = vh;
        }
    } else {
        int j = idx - NH*NP*32;
        if (j < NB*NH*48*32) {
            int bh = j / (48*32);
            int rem = j % (48*32);
            int r = NS + (rem >> 5);
            int dp = rem & 31;
            size_t o = ((size_t)bh * SPAD + r) * 32 + dp;
            g_kh[o] = 0; g_kl[o] = 0; g_vh[o] = 0;
        }
    }
}

// ---------------------------------------------------------------------------
// mma.sync GEMM, all operands pre-split bf16, all-cp.async mainloop.
// C[M,N] = A @ Wt^T, 3-term split (AhBh + AlBh + AhBl).
// CTA 128x128, 256 threads = 8 warps (4m x 2n). K chunks of 64, double buffer.
// Stage smem: Ah 16K | Al 16K | Bh 16K | Bl 16K  (x2 = 128KB)
// MMA schedule: per k16 step, load 16 A-frag regs + 32 B-frag regs, then
// 3 passes of 16 independent MMAs (dep distance 15).
// MODE 0: epilogue scatters split q (x0.125) / k (bf16) / v (fp16).
// MODE 1: epilogue adds bias, writes fp32 d_out.
// ---------------------------------------------------------------------------
#define GEMM_SMEM (2*65536 + 1024)
#define NCH 16

template<int MODE>
__global__ __launch_bounds__(256) void mma_gemm_kernel(
        const unsigned short* __restrict__ Ah_g,
        const unsigned short* __restrict__ Al_g,
        const unsigned short* __restrict__ Wh,
        const unsigned short* __restrict__ Wl,
        const float* __restrict__ bias,
        float* __restrict__ out) {
    extern __shared__ char dsm[];
    const uint32_t sb = (smem_u32(dsm) + 1023u) & ~1023u;

    const int tid = threadIdx.x;
    const int lane = tid & 31;
    const int wm = (tid >> 5) & 3;
    const int wn = tid >> 7;
    const int r0 = blockIdx.y * 128;
    const int c0 = blockIdx.x * 128;

    const uint32_t a_off = (uint32_t)((32*wm + (lane & 15)) * 128 + (lane >> 4) * 16);
    const uint32_t b_off = (uint32_t)((64*wn + ((lane >> 4) & 1) * 8 + (lane & 7)) * 128
                                      + ((lane >> 3) & 1) * 16);
    const int ldrow = tid >> 3;
    const int ldc8  = (tid & 7) * 8;

    float acc[2][8][4];
#pragma unroll
    for (int mf = 0; mf < 2; mf++)
#pragma unroll
        for (int ng = 0; ng < 8; ng++)
#pragma unroll
            for (int c = 0; c < 4; c++) acc[mf][ng][c] = 0.f;

    auto loadStage = [&](int ch, uint32_t bb) {
#pragma unroll
        for (int it = 0; it < 4; ++it) {
            int row = ldrow + it * 32;
            uint32_t off = SW128((uint32_t)(row * 128 + ldc8 * 2));
            size_t ga = (size_t)(r0 + row) * NC + ch * 64 + ldc8;
            CP_ASYNC16(bb + off,           Ah_g + ga);
            CP_ASYNC16(bb + 16384u + off,  Al_g + ga);
            size_t gb = (size_t)(c0 + row) * NC + ch * 64 + ldc8;
            CP_ASYNC16(bb + 32768u + off,  Wh + gb);
            CP_ASYNC16(bb + 49152u + off,  Wl + gb);
        }
    };

    loadStage(0, sb);
    CP_COMMIT();

    for (int ch = 0; ch < NCH; ++ch) {
        const uint32_t base  = sb + (uint32_t)(ch & 1) * 65536u;
        const uint32_t nbase = sb + (uint32_t)((ch & 1) ^ 1) * 65536u;
        if (ch + 1 < NCH) {
            loadStage(ch + 1, nbase);
            CP_COMMIT();
            CP_WAIT1();
        } else {
            CP_WAIT0();
        }
        __syncthreads();   // stage ch visible to all

        const uint32_t bAh = base, bAl = base + 16384u;
        const uint32_t bBh = base + 32768u, bBl = base + 49152u;
#pragma unroll
        for (int kk = 0; kk < 4; ++kk) {
            uint32_t Ahf[2][4], Alf[2][4];
#pragma unroll
            for (int mf = 0; mf < 2; mf++) {
                uint32_t o = a_off + kk * 32 + mf * 2048;
                ldsm_x4(Ahf[mf][0], Ahf[mf][1], Ahf[mf][2], Ahf[mf][3], swz(bAh, o));
                ldsm_x4(Alf[mf][0], Alf[mf][1], Alf[mf][2], Alf[mf][3], swz(bAl, o));
            }
            uint32_t Bhf[4][4], Blf[4][4];
#pragma unroll
            for (int g = 0; g < 4; ++g) {
                uint32_t o = b_off + g * 2048 + kk * 32;
                ldsm_x4(Bhf[g][0], Bhf[g][1], Bhf[g][2], Bhf[g][3], swz(bBh, o));
                ldsm_x4(Blf[g][0], Blf[g][1], Blf[g][2], Blf[g][3], swz(bBl, o));
            }
            // pass 1: Ah x Bh — 16 independent MMAs
#pragma unroll
            for (int g = 0; g < 4; ++g)
#pragma unroll
                for (int mf = 0; mf < 2; mf++) {
                    mma_bf16(acc[mf][2*g],   Ahf[mf], Bhf[g]);
                    mma_bf16(acc[mf][2*g+1], Ahf[mf], Bhf[g] + 2);
                }
            // pass 2: Al x Bh
#pragma unroll
            for (int g = 0; g < 4; ++g)
#pragma unroll
                for (int mf = 0; mf < 2; mf++) {
                    mma_bf16(acc[mf][2*g],   Alf[mf], Bhf[g]);
                    mma_bf16(acc[mf][2*g+1], Alf[mf], Bhf[g] + 2);
                }
            // pass 3: Ah x Bl
#pragma unroll
            for (int g = 0; g < 4; ++g)
#pragma unroll
                for (int mf = 0; mf < 2; mf++) {
                    mma_bf16(acc[mf][2*g],   Ahf[mf], Blf[g]);
                    mma_bf16(acc[mf][2*g+1], Ahf[mf], Blf[g] + 2);
                }
        }
        __syncthreads();   // all reads of 'base' done before ch+2 overwrites
    }

    // ---- epilogue ----
    const int g4 = lane >> 2, t4 = lane & 3;
    const int colb = c0 + 64 * wn;
    const int which = colb >> 10;               // MODE 0 only
    const int hh = (colb >> 6) & (NH - 1);
#pragma unroll
    for (int ng = 0; ng < 8; ++ng) {
        const int col = colb + 8 * ng + 2 * t4;
        const float b0v = bias[col], b1v = bias[col + 1];
#pragma unroll
        for (int mf = 0; mf < 2; mf++) {
            const int row = r0 + 32 * wm + 16 * mf + g4;
            const float* ac = acc[mf][ng];
            if (MODE == 1) {
                float2 v0 = make_float2(ac[0] + b0v, ac[1] + b1v);
                float2 v1 = make_float2(ac[2] + b0v, ac[3] + b1v);
                *(float2*)&out[(size_t)row * NC + col] = v0;
                *(float2*)&out[(size_t)(row + 8) * NC + col] = v1;
            } else {
                const int dp = 4*ng + t4;       // d-pair index 0..31
#pragma unroll
                for (int rr = 0; rr < 2; rr++) {
                    const int r = row + 8*rr;
                    const int b = r >> 11, t = r & (NT - 1);
                    const int bh = b * NH + hh;
                    float x = ac[2*rr] + b0v, y = ac[2*rr+1] + b1v;
                    if (which == 0) {
                        uint32_t h, l;
                        cvt2(x * 0.125f, y * 0.125f, h, l);
                        size_t o = ((size_t)bh * NT + t) * 32 + dp;
                        g_qh[o] = h; g_ql[o] = l;
                    } else if (which == 1) {
                        uint32_t h, l;
                        cvt2(x, y, h, l);
                        size_t o = ((size_t)bh * SPAD + NP + t) * 32 + dp;
                        g_kh[o] = h; g_kl[o] = l;
                    } else {
                        size_t o = ((size_t)bh * SPAD + NP + t) * 32 + dp;
                        g_vh[o] = h2pack(x, y);
                    }
                }
            }
        }
    }
}

// ---------------------------------------------------------------------------
// Tensor-core flash attention (QK MMAs reordered for ILP; split-bf16 output).
// ---------------------------------------------------------------------------
#define ATTN_SMEM (16384*2 + 2*24576 + 1024)
#define NCHUNK 33

__global__ __launch_bounds__(256, 2) void attn_kernel() {
    extern __shared__ char dsm[];
    const uint32_t sb  = (smem_u32(dsm) + 1023u) & ~1023u;
    const uint32_t sQh = sb, sQl = sb + 16384u;
    const uint32_t sBuf0 = sb + 32768u;       // each buf: Kh | Kl | V (8K each)

    const int bh = blockIdx.y;
    const int q0 = blockIdx.x * 128;
    const int b = bh >> 4, h = bh & (NH - 1);
    const int tid = threadIdx.x;
    const int lane = tid & 31;
    const int wid = tid >> 5;

    const uint32_t* Qhp = g_qh + ((size_t)bh * NT + q0) * 32;
    const uint32_t* Qlp = g_ql + ((size_t)bh * NT + q0) * 32;
    const uint32_t* Khp = g_kh + (size_t)bh * SPAD * 32;
    const uint32_t* Klp = g_kl + (size_t)bh * SPAD * 32;
    const uint32_t* Vhp = g_vh + (size_t)bh * SPAD * 32;

    const uint32_t a_off = (uint32_t)((16*wid + (lane & 15)) * 128 + (lane >> 4) * 16);
    const uint32_t b_off = (uint32_t)((((lane >> 4) & 1) * 8 + (lane & 7)) * 128
                                      + ((lane >> 3) & 1) * 16);
    const uint32_t v_off = (uint32_t)((lane & 15) * 128 + (lane >> 4) * 16);

#pragma unroll
    for (int it = 0; it < 8; ++it) {
        int idx = tid + it * 256;
        int ten = idx >> 10;
        int r = (idx & 1023) >> 3;
        int seg = idx & 7;
        const uint32_t* src = (ten ? Qlp : Qhp) + (size_t)r * 32 + seg * 4;
        uint32_t dst = (ten ? sQl : sQh) + SW128((uint32_t)(r * 128 + seg * 16));
        CP_ASYNC16(dst, src);
    }
    auto loadChunk = [&](int ci, uint32_t bb) {
#pragma unroll
        for (int it = 0; it < 6; ++it) {
            int idx = tid + it * 256;
            int ten = idx / 512;
            int r = (idx & 511) >> 3;
            int seg = idx & 7;
            const uint32_t* base = (ten == 0) ? Khp : (ten == 1) ? Klp : Vhp;
            const uint32_t* src = base + (size_t)(ci * 64 + r) * 32 + seg * 4;
            uint32_t dst = bb + (uint32_t)ten * 8192u + SW128((uint32_t)(r * 128 + seg * 16));
            CP_ASYNC16(dst, src);
        }
    };
    loadChunk(0, sBuf0);
    CP_COMMIT();

    float O[8][4];
#pragma unroll
    for (int g = 0; g < 8; g++)
#pragma unroll
        for (int c = 0; c < 4; c++) O[g][c] = 0.f;
    float m0 = -1e30f, m1 = -1e30f, l0 = 0.f, l1 = 0.f;

    for (int ci = 0; ci < NCHUNK; ++ci) {
        const uint32_t buf  = sBuf0 + (uint32_t)(ci & 1) * 24576u;
        const uint32_t nbuf = sBuf0 + (uint32_t)((ci & 1) ^ 1) * 24576u;
        if (ci + 1 < NCHUNK) {
            loadChunk(ci + 1, nbuf);
            CP_COMMIT();
            CP_WAIT1();
        } else {
            CP_WAIT0();
        }
        __syncthreads();

        const uint32_t bKh = buf, bKl = buf + 8192u, bV = buf + 16384u;

        // ---- S = Q K^T (3-term split), gg processed in pairs for ILP ----
        float S[8][4];
#pragma unroll
        for (int g = 0; g < 8; g++)
#pragma unroll
            for (int c = 0; c < 4; c++) S[g][c] = 0.f;
#pragma unroll
        for (int kk = 0; kk < 4; ++kk) {
            uint32_t Ahf[4], Alf[4];
            ldsm_x4(Ahf[0], Ahf[1], Ahf[2], Ahf[3], swz(sQh, a_off + kk * 32));
            ldsm_x4(Alf[0], Alf[1], Alf[2], Alf[3], swz(sQl, a_off + kk * 32));
#pragma unroll
            for (int gp = 0; gp < 2; ++gp) {
                uint32_t K0h[4], K0l[4], K1h[4], K1l[4];
                uint32_t o0 = b_off + (2*gp) * 2048 + kk * 32;
                uint32_t o1 = b_off + (2*gp+1) * 2048 + kk * 32;
                ldsm_x4(K0h[0], K0h[1], K0h[2], K0h[3], swz(bKh, o0));
                ldsm_x4(K0l[0], K0l[1], K0l[2], K0l[3], swz(bKl, o0));
                ldsm_x4(K1h[0], K1h[1], K1h[2], K1h[3], swz(bKh, o1));
                ldsm_x4(K1l[0], K1l[1], K1l[2], K1l[3], swz(bKl, o1));
                float* s0 = S[4*gp];
                float* s1 = S[4*gp+1];
                float* s2 = S[4*gp+2];
                float* s3 = S[4*gp+3];
                // pass 1: Qh x Kh (4 independent)
                mma_bf16(s0, Ahf, K0h); mma_bf16(s1, Ahf, K0h + 2);
                mma_bf16(s2, Ahf, K1h); mma_bf16(s3, Ahf, K1h + 2);
                // pass 2: Ql x Kh
                mma_bf16(s0, Alf, K0h); mma_bf16(s1, Alf, K0h + 2);
                mma_bf16(s2, Alf, K1h); mma_bf16(s3, Alf, K1h + 2);
                // pass 3: Qh x Kl
                mma_bf16(s0, Ahf, K0l); mma_bf16(s1, Ahf, K0l + 2);
                mma_bf16(s2, Ahf, K1l); mma_bf16(s3, Ahf, K1l + 2);
            }
        }

        // ---- tail mask (chunk 32: only cols 0..15 valid => frags g>=2) ----
        if (ci == NCHUNK - 1) {
#pragma unroll
            for (int g = 2; g < 8; g++)
#pragma unroll
                for (int c = 0; c < 4; c++) S[g][c] = -1e30f;
        }

        // ---- online softmax ----
        float tm0 = -1e30f, tm1 = -1e30f;
#pragma unroll
        for (int g = 0; g < 8; g++) {
            tm0 = fmaxf(tm0, fmaxf(S[g][0], S[g][1]));
            tm1 = fmaxf(tm1, fmaxf(S[g][2], S[g][3]));
        }
        tm0 = fmaxf(tm0, __shfl_xor_sync(0xffffffffu, tm0, 1));
        tm0 = fmaxf(tm0, __shfl_xor_sync(0xffffffffu, tm0, 2));
        tm1 = fmaxf(tm1, __shfl_xor_sync(0xffffffffu, tm1, 1));
        tm1 = fmaxf(tm1, __shfl_xor_sync(0xffffffffu, tm1, 2));
        float mn0 = fmaxf(m0, tm0), mn1 = fmaxf(m1, tm1);
        float al0 = __expf(m0 - mn0), al1 = __expf(m1 - mn1);
        float s0 = 0.f, s1 = 0.f;
#pragma unroll
        for (int g = 0; g < 8; g++) {
            S[g][0] = __expf(S[g][0] - mn0);
            S[g][1] = __expf(S[g][1] - mn0);
            S[g][2] = __expf(S[g][2] - mn1);
            S[g][3] = __expf(S[g][3] - mn1);
            s0 += S[g][0] + S[g][1];
            s1 += S[g][2] + S[g][3];
        }
        s0 += __shfl_xor_sync(0xffffffffu, s0, 1);
        s0 += __shfl_xor_sync(0xffffffffu, s0, 2);
        s1 += __shfl_xor_sync(0xffffffffu, s1, 1);
        s1 += __shfl_xor_sync(0xffffffffu, s1, 2);
        l0 = l0 * al0 + s0; l1 = l1 * al1 + s1;
        m0 = mn0; m1 = mn1;
#pragma unroll
        for (int g = 0; g < 8; g++) {
            O[g][0] *= al0; O[g][1] *= al0;
            O[g][2] *= al1; O[g][3] *= al1;
        }

        // ---- pack P to fp16 A-frags ----
        uint32_t pa[4][4];
#pragma unroll
        for (int kk = 0; kk < 4; ++kk) {
            pa[kk][0] = h2pack(S[2*kk][0],   S[2*kk][1]);
            pa[kk][1] = h2pack(S[2*kk][2],   S[2*kk][3]);
            pa[kk][2] = h2pack(S[2*kk+1][0], S[2*kk+1][1]);
            pa[kk][3] = h2pack(S[2*kk+1][2], S[2*kk+1][3]);
        }

        // ---- O += P V ----
#pragma unroll
        for (int kk = 0; kk < 4; ++kk) {
#pragma unroll
            for (int gg = 0; gg < 4; ++gg) {
                uint32_t Vb[4];
                uint32_t o = v_off + kk * 2048 + gg * 32;
                ldsm_x4t(Vb[0], Vb[1], Vb[2], Vb[3], swz(bV, o));
                mma_f16(O[2*gg],   pa[kk], Vb);
                mma_f16(O[2*gg+1], pa[kk], Vb + 2);
            }
        }
        __syncthreads();
    }

    // ---- epilogue: normalize, split to bf16 hi/lo, write g_ath/g_atl ----
    const float inv0 = 1.f / l0, inv1 = 1.f / l1;
    const int r = lane >> 2;
    const int row0 = q0 + 16*wid + r;
#pragma unroll
    for (int g = 0; g < 8; g++) {
        const int dp = h * 32 + 4*g + (lane & 3);   // pair index within row
        uint32_t hh, ll;
        cvt2(O[g][0] * inv0, O[g][1] * inv0, hh, ll);
        size_t o0 = (size_t)(b*NT + row0) * 512 + dp;
        g_ath[o0] = hh; g_atl[o0] = ll;
        cvt2(O[g][2] * inv1, O[g][3] * inv1, hh, ll);
        size_t o1 = (size_t)(b*NT + row0 + 8) * 512 + dp;
        g_ath[o1] = hh; g_atl[o1] = ll;
    }
}

// ---------------------------------------------------------------------------
// Launch
// ---------------------------------------------------------------------------
extern "C" void kernel_launch(void* const* d_in, const int* in_sizes, int n_in,
                              void* d_out, int out_size) {
    const float* x    = (const float*)d_in[0];
    const float* pk   = (const float*)d_in[1];
    const float* pv   = (const float*)d_in[2];
    const float* Wqkv = (const float*)d_in[3];
    const float* bqkv = (const float*)d_in[4];
    const float* Wout = (const float*)d_in[5];
    const float* bout = (const float*)d_in[6];
    float* out = (float*)d_out;

    cudaFuncSetAttribute(attn_kernel,
                         cudaFuncAttributeMaxDynamicSharedMemorySize, ATTN_SMEM);
    cudaFuncSetAttribute(mma_gemm_kernel<0>,
                         cudaFuncAttributeMaxDynamicSharedMemorySize, GEMM_SMEM);
    cudaFuncSetAttribute(mma_gemm_kernel<1>,
                         cudaFuncAttributeMaxDynamicSharedMemorySize, GEMM_SMEM);

    unsigned short *wqh, *wql, *woh, *wol, *xh, *xl, *ath, *atl;
    cudaGetSymbolAddress((void**)&wqh, g_wqkv_h);
    cudaGetSymbolAddress((void**)&wql, g_wqkv_l);
    cudaGetSymbolAddress((void**)&woh, g_wout_h);
    cudaGetSymbolAddress((void**)&wol, g_wout_l);
    cudaGetSymbolAddress((void**)&xh,  g_xh);
    cudaGetSymbolAddress((void**)&xl,  g_xl);
    cudaGetSymbolAddress((void**)&ath, g_ath);
    cudaGetSymbolAddress((void**)&atl, g_atl);

    dim3 tb(32, 8);
    wprep_kernel<<<dim3(96, 32), tb>>>(Wqkv, 3*NC, wqh, wql);
    wprep_kernel<<<dim3(32, 32), tb>>>(Wout,   NC, woh, wol);
    prefix_fill_kernel<<<224, 256>>>(pk, pv);
    xprep_kernel<<<NROWS*(NC/2)/256, 256>>>(x);

    mma_gemm_kernel<0><<<dim3(24, 32), 256, GEMM_SMEM>>>(xh, xl, wqh, wql, bqkv, nullptr);
    attn_kernel<<<dim3(16, 32), 256, ATTN_SMEM>>>();
    mma_gemm_kernel<1><<<dim3(8, 32), 256, GEMM_SMEM>>>(ath, atl, woh, wol, bout, out);
}